// round 12
// baseline (speedup 1.0000x reference)
#include <cuda_runtime.h>
#include <cstdint>
#include <cstddef>

// Problem constants
#define TT   255
#define BB   256
#define KK   784
#define NN   40
#define MM   (TT * BB)          // 65280
#define PLANE (BB * NN)         // 10240 elements per timestep
#define OUT_HALF (TT * PLANE)   // 2,611,200

// Scratch for cur = x @ W^T   (10.44 MB, static device global: allowed)
__device__ float g_cur[(size_t)MM * NN];

// packed f32x2 FMA: d = fma(a, b, d) per lane (IEEE rn, fused)
__device__ __forceinline__ void fma2(unsigned long long& d,
                                     unsigned long long a,
                                     unsigned long long b) {
    asm("fma.rn.f32x2 %0, %1, %2, %3;" : "=l"(d) : "l"(a), "l"(b), "l"(d));
}
// packed f32x2 add (rn)
__device__ __forceinline__ unsigned long long add2(unsigned long long a,
                                                   unsigned long long b) {
    unsigned long long d;
    asm("add.rn.f32x2 %0, %1, %2;" : "=l"(d) : "l"(a), "l"(b));
    return d;
}

// ---------------------------------------------------------------------------
// Kernel 1: cur[m][n] = sum_k x[m][k] * W[n][k]
//
// Rounding scheme (bit-identical to all passing rounds):
//   8 chains, chain j = fused-FMA over k ≡ j (mod 8) ascending;
//   combine: ((c0+c4)+(c1+c5)) + ((c2+c6)+(c3+c7))
//   realized by phase-per-thread + butterfly shuffles xor {4,1,2}.
//
// R12 RESTRUCTURE: 512-thread blocks, 1 CTA/SM (same 16 warps/SM as before)
//   8 phases x 64 workers = 8 row-groups (TM=8) x 8 col-groups (TN=5,
//   columns n = wcolg + 8*cc). Accumulators: 20 FMA2 = 40 regs (was 80)
//   -> comfortably under the cap, NO spills in the hot loop.
// Staging roles disjoint: threads 0-255 load A, 256-415 load W.
// Software-pipelined double buffering, prefetch distance 2, 1 barrier/chunk.
// As stride 68 floats (A LDS.128 conflict-free); Ws2 stride 41 float2
// (9k mod 16 distinct bank-pairs across the 8 phases, 1-wavefront broadcast).
// ---------------------------------------------------------------------------
#define NCHUNK (KK / 16)    // 49

__global__ __launch_bounds__(512, 1)
void snn_gemm_kernel(const float* __restrict__ x, const float* __restrict__ W) {
    __shared__ float  As[2][16][68];
    __shared__ float2 Ws2[2][16][41];

    const int tid   = threadIdx.x;
    const int phase = tid & 7;          // chain index 0..7
    const int ww    = tid >> 3;         // worker 0..63
    const int wrow  = ww & 7;           // 8 row groups * TM=8 -> BM=64
    const int wcolg = ww >> 3;          // 8 col groups, n = wcolg + 8*cc
    const int mbase = blockIdx.x * 64;

    // Disjoint staging roles
    const bool arole = (tid < 256);             // A: 64 rows x 4 float4
    const bool wrole = (tid >= 256 && tid < 416); // W: 40 n x 4 float4
    const int arow = tid >> 2;                  // aroles: 0..63
    const int aq   = tid & 3;
    const int widx = tid - 256;
    const int wn   = widx >> 2;                 // wroles: 0..39
    const int wq   = widx & 3;
    const float* __restrict__ aptr =
        x + (size_t)(mbase + (arow & 63)) * KK + aq * 4;
    const float* __restrict__ wptr =
        W + (size_t)(wn & 63) * KK + wq * 4;

    float4 a_st = make_float4(0.f, 0.f, 0.f, 0.f);
    float4 w_st = make_float4(0.f, 0.f, 0.f, 0.f);

    // ---- prologue: chunk 0 -> smem stage 0; chunk 1 -> regs ----
    if (arole) a_st = *reinterpret_cast<const float4*>(aptr);
    if (wrole) w_st = *reinterpret_cast<const float4*>(wptr);
    if (arole) {
        As[0][aq * 4 + 0][arow] = a_st.x;
        As[0][aq * 4 + 1][arow] = a_st.y;
        As[0][aq * 4 + 2][arow] = a_st.z;
        As[0][aq * 4 + 3][arow] = a_st.w;
    }
    if (wrole) {
        Ws2[0][wq * 4 + 0][wn] = make_float2(w_st.x, w_st.x);
        Ws2[0][wq * 4 + 1][wn] = make_float2(w_st.y, w_st.y);
        Ws2[0][wq * 4 + 2][wn] = make_float2(w_st.z, w_st.z);
        Ws2[0][wq * 4 + 3][wn] = make_float2(w_st.w, w_st.w);
    }
    if (arole) a_st = *reinterpret_cast<const float4*>(aptr + 16);
    if (wrole) w_st = *reinterpret_cast<const float4*>(wptr + 16);
    __syncthreads();

    unsigned long long acc[4][5];
    #pragma unroll
    for (int i = 0; i < 4; ++i)
        #pragma unroll
        for (int c = 0; c < 5; ++c) acc[i][c] = 0ULL;

    for (int c = 0; c < NCHUNK; ++c) {
        const int nb = (c + 1) & 1;
        // STS chunk c+1 (in regs) into the other buffer
        if (c < NCHUNK - 1) {
            if (arole) {
                As[nb][aq * 4 + 0][arow] = a_st.x;
                As[nb][aq * 4 + 1][arow] = a_st.y;
                As[nb][aq * 4 + 2][arow] = a_st.z;
                As[nb][aq * 4 + 3][arow] = a_st.w;
            }
            if (wrole) {
                Ws2[nb][wq * 4 + 0][wn] = make_float2(w_st.x, w_st.x);
                Ws2[nb][wq * 4 + 1][wn] = make_float2(w_st.y, w_st.y);
                Ws2[nb][wq * 4 + 2][wn] = make_float2(w_st.z, w_st.z);
                Ws2[nb][wq * 4 + 3][wn] = make_float2(w_st.w, w_st.w);
            }
        }
        // LDG chunk c+2 -> regs (in flight during compute below)
        if (c + 2 < NCHUNK) {
            if (arole) a_st = *reinterpret_cast<const float4*>(aptr + (c + 2) * 16);
            if (wrole) w_st = *reinterpret_cast<const float4*>(wptr + (c + 2) * 16);
        }

        // compute chunk c from stage c&1
        const int s = c & 1;
        #pragma unroll
        for (int half = 0; half < 2; ++half) {
            const int k = phase + half * 8;     // ascending within chain
            ulonglong2 A0 = *reinterpret_cast<const ulonglong2*>(&As[s][k][wrow * 8]);
            ulonglong2 A1 = *reinterpret_cast<const ulonglong2*>(&As[s][k][wrow * 8 + 4]);
            #pragma unroll
            for (int cc = 0; cc < 5; ++cc) {
                unsigned long long b = *reinterpret_cast<const unsigned long long*>(
                    &Ws2[s][k][wcolg + 8 * cc]);
                fma2(acc[0][cc], A0.x, b);
                fma2(acc[1][cc], A0.y, b);
                fma2(acc[2][cc], A1.x, b);
                fma2(acc[3][cc], A1.y, b);
            }
        }
        __syncthreads();   // single barrier: STS(c+1) visible; readers of stage s done
    }

    // Cross-phase combine: butterfly xor {4,1,2} == exact pairwise tree
    #pragma unroll
    for (int i = 0; i < 4; ++i) {
        #pragma unroll
        for (int cc = 0; cc < 5; ++cc) {
            unsigned long long v = acc[i][cc];
            v = add2(v, __shfl_xor_sync(0xFFFFFFFFu, v, 4));
            v = add2(v, __shfl_xor_sync(0xFFFFFFFFu, v, 1));
            v = add2(v, __shfl_xor_sync(0xFFFFFFFFu, v, 2));
            if (phase == 0) {
                const int n  = wcolg + 8 * cc;
                const int m0 = mbase + wrow * 8 + i * 2;
                g_cur[(size_t)m0 * NN + n] =
                    __uint_as_float((unsigned int)(v & 0xFFFFFFFFu));
                g_cur[(size_t)(m0 + 1) * NN + n] =
                    __uint_as_float((unsigned int)(v >> 32));
            }
        }
    }
}

// ---------------------------------------------------------------------------
// Kernel 2: LIF recurrence; 2 cells per thread (float2 I/O, ILP 2).
//   mem_new = select(mem > 1, 0, unfused(0.95*mem + cur))   [== reference]
//   spk = (mem_new > 1)  [sign-exact vs (mem-1 > 0) via Sterbenz]
// Ring-buffer prefetch DEEPENED to 32: g_cur reads can miss L2 (evicted by
// the 205MB x stream) -> ~600cyc DRAM latency needs ~32 outstanding loads.
// ---------------------------------------------------------------------------
#define P2 (PLANE / 2)   // 5120 float2 per timestep

__global__ __launch_bounds__(32)
void snn_scan_kernel(float* __restrict__ out) {
    const int j = blockIdx.x * 32 + threadIdx.x;      // < 5120
    const float2* __restrict__ cp = reinterpret_cast<const float2*>(g_cur) + j;
    float2* __restrict__ sp = reinterpret_cast<float2*>(out) + j;
    float2* __restrict__ mp = reinterpret_cast<float2*>(out + OUT_HALF) + j;

    float2 buf[32];
    #pragma unroll
    for (int i = 0; i < 32; ++i) buf[i] = cp[(size_t)i * P2];

    float m0 = 0.0f, m1 = 0.0f;

    // 255 = 7*32 + 31: main t = 0..223, tail t = 224..254
    for (int t0 = 0; t0 < 224; t0 += 32) {
        #pragma unroll
        for (int u = 0; u < 32; ++u) {
            int t = t0 + u;
            float2 c = buf[u];
            int tn = t + 32; if (tn > TT - 1) tn = TT - 1;
            buf[u] = cp[(size_t)tn * P2];
            float n0 = __fadd_rn(__fmul_rn(0.95f, m0), c.x);
            float n1 = __fadd_rn(__fmul_rn(0.95f, m1), c.y);
            m0 = (m0 > 1.0f) ? 0.0f : n0;
            m1 = (m1 > 1.0f) ? 0.0f : n1;
            sp[(size_t)t * P2] = make_float2((m0 > 1.0f) ? 1.0f : 0.0f,
                                             (m1 > 1.0f) ? 1.0f : 0.0f);
            mp[(size_t)t * P2] = make_float2(m0, m1);
        }
    }
    #pragma unroll
    for (int u = 0; u < 31; ++u) {
        int t = 224 + u;
        float2 c = buf[u];
        float n0 = __fadd_rn(__fmul_rn(0.95f, m0), c.x);
        float n1 = __fadd_rn(__fmul_rn(0.95f, m1), c.y);
        m0 = (m0 > 1.0f) ? 0.0f : n0;
        m1 = (m1 > 1.0f) ? 0.0f : n1;
        sp[(size_t)t * P2] = make_float2((m0 > 1.0f) ? 1.0f : 0.0f,
                                         (m1 > 1.0f) ? 1.0f : 0.0f);
        mp[(size_t)t * P2] = make_float2(m0, m1);
    }
}

// ---------------------------------------------------------------------------
extern "C" void kernel_launch(void* const* d_in, const int* in_sizes, int n_in,
                              void* d_out, int out_size) {
    const float* x = (const float*)d_in[0];
    const float* W = (const float*)d_in[1];
    // Defensive: metadata order should be (x, W); swap if sizes say otherwise.
    if (n_in >= 2 && in_sizes[0] == NN * KK) {
        const float* t = x; x = W; W = t;
    }
    float* out = (float*)d_out;

    snn_gemm_kernel<<<MM / 64, 512>>>(x, W);    // 1020 blocks, 1 CTA/SM
    snn_scan_kernel<<<P2 / 32, 32>>>(out);      // 160 blocks
}